// round 12
// baseline (speedup 1.0000x reference)
#include <cuda_runtime.h>

// ParametricInterpolation — numerics FROZEN (bit-exact vs reference since R8):
//   p_k = RN(params_k * RN(1/fl32(scaler_k)))   (XLA divide->recip-mul)
//   i2 = RN(i*i), i3 = RN(i2*i), i4 = RN(i2*i2) (integer_pow sq-and-mul)
//   c  = RN(p0*i4); fma(p1,i3); fma(p2,i2); fma(p3,i); + p4  (ascending fma)
//   ci = rintf(c); k = c - ci; pos = clip(i - ci, 1, 2047)
//   out = RN(RN(x1*RN(1-k)) + RN(x2*k))          (non-contracted lerp)
//
// Perf change vs R11: chunked phases (2 chunks x 4 parts) so the live value
// set fits in ~30 registers — R11 held 32 spilled-to-local values under the
// 32-reg occupancy-8 cap (L1=41% with no smem = LDL/STL traffic). Gathers
// stay direct-from-global, warp-consecutive (coalesced; x[pos-1] L1-hits).

#define SIG_LEN 2048
#define PARTS   (SIG_LEN / 256)   // 8
#define CHUNK   4                 // parts per chunk

__global__ __launch_bounds__(256, 7)
void pik_kernel(const float* __restrict__ x,
                const float* __restrict__ params,
                float* __restrict__ out)
{
    const int b   = blockIdx.x;
    const int tid = threadIdx.x;

    // Warp-uniform param loads -> broadcast, L1-resident.
    const float* pb = params + (size_t)b * 5;
    const float p0 = __fmul_rn(__ldg(pb + 0), (float)(1.0 / (double)1e12f));
    const float p1 = __fmul_rn(__ldg(pb + 1), (float)(1.0 / (double)1e8f));
    const float p2 = __fmul_rn(__ldg(pb + 2), (float)(1.0 / (double)1e4f));
    const float p3 =            __ldg(pb + 3);   // inv = 1.0 exactly
    const float p4 = __fmul_rn(__ldg(pb + 4), (float)(1.0 / (double)10.0f));

    const float* xrow = x   + (size_t)b * SIG_LEN;
    float*       orow = out + (size_t)b * SIG_LEN;

    #pragma unroll
    for (int chunk = 0; chunk < PARTS / CHUNK; ++chunk) {
        int   pos[CHUNK];
        float kk [CHUNK];

        // Phase 1: indices/weights for this chunk (pure ALU).
        #pragma unroll
        for (int part = 0; part < CHUNK; ++part) {
            const int n = (chunk * CHUNK + part) * 256 + tid;
            const float fi = (float)n;

            const float i2 = __fmul_rn(fi, fi);   // exact
            const float i3 = __fmul_rn(i2, fi);
            const float i4 = __fmul_rn(i2, i2);

            float c = __fmul_rn(p0, i4);          // ascending-k fma chain
            c = __fmaf_rn(p1, i3, c);
            c = __fmaf_rn(p2, i2, c);
            c = __fmaf_rn(p3, fi, c);
            c = __fadd_rn(c, p4);

            const float ci = rintf(c);            // round half to even
            kk[part] = __fadd_rn(c, -ci);

            float posf = fi - ci;                 // exact: integer-valued floats
            posf = fminf(fmaxf(posf, 1.0f), (float)(SIG_LEN - 1));
            pos[part] = (int)posf;
        }

        // Phase 2: 8 independent gather LDGs in flight.
        float x1v[CHUNK], x2v[CHUNK];
        #pragma unroll
        for (int part = 0; part < CHUNK; ++part) {
            x1v[part] = __ldg(xrow + pos[part]);
            x2v[part] = __ldg(xrow + pos[part] - 1);
        }

        // Phase 3: lerp + coalesced stores.
        #pragma unroll
        for (int part = 0; part < CHUNK; ++part) {
            const int n = (chunk * CHUNK + part) * 256 + tid;
            const float k  = kk[part];
            const float w1 = __fsub_rn(1.0f, k);  // non-contracted lerp
            orow[n] = __fadd_rn(__fmul_rn(x1v[part], w1), __fmul_rn(x2v[part], k));
        }
    }
}

extern "C" void kernel_launch(void* const* d_in, const int* in_sizes, int n_in,
                              void* d_out, int out_size)
{
    const float* x;
    const float* params;
    if (n_in >= 2 && in_sizes[0] < in_sizes[1]) {
        params = (const float*)d_in[0];
        x      = (const float*)d_in[1];
    } else {
        x      = (const float*)d_in[0];
        params = (const float*)d_in[1];
    }
    float* out = (float*)d_out;

    const int batch = 16384;
    pik_kernel<<<batch, 256>>>(x, params, out);
}